// round 9
// baseline (speedup 1.0000x reference)
#include <cuda_runtime.h>
#include <cuda_bf16.h>
#include <cstdint>

// Problem constants (fixed by dataset)
#define BATCH 16
#define NNODE 16384
#define DIM   128
#define NEDGE 65536
#define TOTAL_NODES (BATCH * NNODE)   // 262144
#define LN_EPS 1e-5f

// ---------------- device scratch (no allocs allowed) ----------------
// 16B-aligned: all are accessed via float4.
__device__ __align__(16) float g_neigh[(size_t)TOTAL_NODES * DIM];   // 134 MB aggregated features
__device__ __align__(16) float g_WT[256 * 128];                      // [Wself;Wneigh]^T: WT[k][n]
__device__ int   g_deg[NNODE];
__device__ int   g_rowstart[NNODE + 1];
__device__ int   g_cursor[NNODE];
__device__ int   g_csr[NEDGE];

// ---------------- small setup kernels ----------------
__global__ void zero_kernel() {
    int i = blockIdx.x * blockDim.x + threadIdx.x;
    if (i < NNODE) { g_deg[i] = 0; g_cursor[i] = 0; }
}

// NOTE: edge_index arrives as int32 (JAX x64 disabled downcasts jnp.int64 -> int32).
__global__ void count_kernel(const int* __restrict__ edge) {
    int e = blockIdx.x * blockDim.x + threadIdx.x;
    if (e < NEDGE) {
        int dst = edge[NEDGE + e];
        atomicAdd(&g_deg[dst], 1);
    }
}

// single-block exclusive scan over 16384 degrees
__global__ void scan_kernel() {
    __shared__ int sums[1024];
    int t = threadIdx.x;
    int base = t * 16;
    int local[16];
    int s = 0;
#pragma unroll
    for (int i = 0; i < 16; i++) { local[i] = s; s += g_deg[base + i]; }
    sums[t] = s;
    __syncthreads();
    for (int off = 1; off < 1024; off <<= 1) {
        int v = 0;
        if (t >= off) v = sums[t - off];
        __syncthreads();
        sums[t] += v;
        __syncthreads();
    }
    int excl = (t == 0) ? 0 : sums[t - 1];
#pragma unroll
    for (int i = 0; i < 16; i++) g_rowstart[base + i] = excl + local[i];
    if (t == 1023) g_rowstart[NNODE] = sums[1023];
}

__global__ void fill_kernel(const int* __restrict__ edge) {
    int e = blockIdx.x * blockDim.x + threadIdx.x;
    if (e < NEDGE) {
        int src = edge[e];
        int dst = edge[NEDGE + e];
        int pos = atomicAdd(&g_cursor[dst], 1);
        g_csr[g_rowstart[dst] + pos] = src;
    }
}

// transpose + concat weights: WT[k][n], k<128 -> Wself[n][k], k>=128 -> Wneigh[n][k-128]
__global__ void wt_kernel(const float* __restrict__ Ws, const float* __restrict__ Wn) {
    int idx = blockIdx.x * blockDim.x + threadIdx.x;
    if (idx < 256 * 128) {
        int k = idx >> 7, n = idx & 127;
        g_WT[idx] = (k < 128) ? Ws[n * 128 + k] : Wn[n * 128 + (k - 128)];
    }
}

// ---------------- neighbor mean via CSR gather (no heavy atomics) ----------------
__global__ __launch_bounds__(256) void neigh_kernel(const float* __restrict__ x) {
    int gwarp = (blockIdx.x * 256 + threadIdx.x) >> 5;   // one warp per (batch,node)
    int lane = threadIdx.x & 31;
    int b = gwarp >> 14;            // / 16384
    int n = gwarp & (NNODE - 1);
    int s0 = g_rowstart[n];
    int s1 = g_rowstart[n + 1];
    const float* xb = x + ((size_t)b << 14) * DIM;
    float4 acc = make_float4(0.f, 0.f, 0.f, 0.f);
    for (int j = s0; j < s1; j++) {
        int src = g_csr[j];
        float4 v = *(const float4*)(xb + (size_t)src * DIM + lane * 4);
        acc.x += v.x; acc.y += v.y; acc.z += v.z; acc.w += v.w;
    }
    int deg = s1 - s0;
    float inv = 1.0f / (float)(deg > 0 ? deg : 1);
    acc.x *= inv; acc.y *= inv; acc.z *= inv; acc.w *= inv;
    *(float4*)(g_neigh + (size_t)gwarp * DIM + lane * 4) = acc;
}

// ---------------- fused dual-GEMM + bias + LayerNorm + ReLU ----------------
// tile: 128 rows x 128 cols, K=256 (phase 0 = x@WselfT, phase 1 = neigh@WneighT)
// 256 threads, each computes 8 rows x 8 cols with plain FFMA (no inline asm).
__global__ __launch_bounds__(256) void gemm_ln_kernel(
    const float* __restrict__ x,
    const float* __restrict__ bias,
    const float* __restrict__ gamma,
    const float* __restrict__ beta,
    float* __restrict__ out)
{
    __shared__ float As[128 * 16];   // [row][k], stride 16
    __shared__ float Bs[16 * 128];   // [k][n]

    int tid = threadIdx.x;
    int tx = tid & 15;     // col group: cols tx*8 .. tx*8+7
    int ty = tid >> 4;     // row group: rows ty*8 .. ty*8+7
    int row0 = blockIdx.x * 128;

    float acc[8][8];
#pragma unroll
    for (int i = 0; i < 8; i++)
#pragma unroll
        for (int j = 0; j < 8; j++) acc[i][j] = 0.f;

#pragma unroll 1
    for (int phase = 0; phase < 2; ++phase) {
        const float* A = phase ? g_neigh : x;
        int wko = phase * 128;
#pragma unroll 1
        for (int kk = 0; kk < 128; kk += 16) {
            // load A tile: 128 rows x 16 k  (512 float4, 2 per thread)
#pragma unroll
            for (int l = 0; l < 2; l++) {
                int idx = tid + l * 256;
                int r = idx >> 2, q = idx & 3;
                float4 v = *(const float4*)(A + (size_t)(row0 + r) * DIM + kk + q * 4);
                *(float4*)(As + r * 16 + q * 4) = v;
            }
            // load B tile: 16 k-rows x 128 n (coalesced from pre-transposed WT)
#pragma unroll
            for (int l = 0; l < 2; l++) {
                int idx = tid + l * 256;
                int k = idx >> 5, q = idx & 31;
                float4 v = *(const float4*)(g_WT + (size_t)(wko + kk + k) * 128 + q * 4);
                *(float4*)(Bs + k * 128 + q * 4) = v;
            }
            __syncthreads();
#pragma unroll
            for (int k = 0; k < 16; k++) {
                float4 b0 = *(const float4*)(Bs + k * 128 + tx * 8);
                float4 b1 = *(const float4*)(Bs + k * 128 + tx * 8 + 4);
                float b[8] = { b0.x, b0.y, b0.z, b0.w, b1.x, b1.y, b1.z, b1.w };
                float a[8];
#pragma unroll
                for (int i = 0; i < 8; i++) a[i] = As[(ty * 8 + i) * 16 + k];
#pragma unroll
                for (int i = 0; i < 8; i++)
#pragma unroll
                    for (int j = 0; j < 8; j++)
                        acc[i][j] = fmaf(a[i], b[j], acc[i][j]);
            }
            __syncthreads();
        }
    }

    // epilogue: bias -> LayerNorm over 128 cols (16 contiguous lanes per row) -> relu
    float bi[8], ga[8], be[8];
#pragma unroll
    for (int j = 0; j < 8; j++) {
        int col = tx * 8 + j;
        bi[j] = bias[col]; ga[j] = gamma[col]; be[j] = beta[col];
    }

#pragma unroll
    for (int i = 0; i < 8; i++) {
        float c[8];
#pragma unroll
        for (int j = 0; j < 8; j++) c[j] = acc[i][j] + bi[j];

        float s = 0.f;
#pragma unroll
        for (int j = 0; j < 8; j++) s += c[j];
#pragma unroll
        for (int m = 1; m < 16; m <<= 1) s += __shfl_xor_sync(0xffffffffu, s, m);
        float mean = s * (1.0f / 128.0f);

        float sq = 0.f;
#pragma unroll
        for (int j = 0; j < 8; j++) { float d = c[j] - mean; sq += d * d; }
#pragma unroll
        for (int m = 1; m < 16; m <<= 1) sq += __shfl_xor_sync(0xffffffffu, sq, m);
        float rstd = rsqrtf(sq * (1.0f / 128.0f) + LN_EPS);

        float4 o0, o1;
        float v;
        v = (c[0] - mean) * rstd * ga[0] + be[0]; o0.x = fmaxf(v, 0.f);
        v = (c[1] - mean) * rstd * ga[1] + be[1]; o0.y = fmaxf(v, 0.f);
        v = (c[2] - mean) * rstd * ga[2] + be[2]; o0.z = fmaxf(v, 0.f);
        v = (c[3] - mean) * rstd * ga[3] + be[3]; o0.w = fmaxf(v, 0.f);
        v = (c[4] - mean) * rstd * ga[4] + be[4]; o1.x = fmaxf(v, 0.f);
        v = (c[5] - mean) * rstd * ga[5] + be[5]; o1.y = fmaxf(v, 0.f);
        v = (c[6] - mean) * rstd * ga[6] + be[6]; o1.z = fmaxf(v, 0.f);
        v = (c[7] - mean) * rstd * ga[7] + be[7]; o1.w = fmaxf(v, 0.f);

        size_t row = (size_t)(row0 + ty * 8 + i);
        *(float4*)(out + row * DIM + tx * 8)     = o0;
        *(float4*)(out + row * DIM + tx * 8 + 4) = o1;
    }
}

// ---------------- launch ----------------
extern "C" void kernel_launch(void* const* d_in, const int* in_sizes, int n_in,
                              void* d_out, int out_size)
{
    // robust input mapping by element count
    const float* x = nullptr;
    const int* edge = nullptr;          // int32 on the wire (JAX x64 disabled)
    const float* Ws = nullptr; const float* Wn = nullptr;
    const float* bias = nullptr; const float* gamma = nullptr; const float* beta = nullptr;
    int w_seen = 0, v_seen = 0;
    for (int i = 0; i < n_in; i++) {
        int sz = in_sizes[i];
        if (sz == TOTAL_NODES * DIM) {
            x = (const float*)d_in[i];
        } else if (sz == 2 * NEDGE) {
            edge = (const int*)d_in[i];
        } else if (sz == 128 * 128) {
            if (w_seen == 0) Ws = (const float*)d_in[i];
            else             Wn = (const float*)d_in[i];
            w_seen++;
        } else if (sz == 128) {
            if (v_seen == 0)      bias  = (const float*)d_in[i];
            else if (v_seen == 1) gamma = (const float*)d_in[i];
            else                  beta  = (const float*)d_in[i];
            v_seen++;
        }
    }
    float* out = (float*)d_out;

    // 1. CSR build (edge structure is batch-invariant)
    zero_kernel<<<(NNODE + 255) / 256, 256>>>();
    count_kernel<<<(NEDGE + 255) / 256, 256>>>(edge);
    scan_kernel<<<1, 1024>>>();
    fill_kernel<<<(NEDGE + 255) / 256, 256>>>(edge);

    // 2. transpose+concat weights
    wt_kernel<<<(256 * 128 + 255) / 256, 256>>>(Ws, Wn);

    // 3. neighbor mean (gather via CSR, 8 node-warps per block)
    neigh_kernel<<<TOTAL_NODES / 8, 256>>>(x);

    // 4. fused dual-GEMM + bias + LayerNorm + ReLU
    gemm_ln_kernel<<<TOTAL_NODES / 128, 256>>>(x, bias, gamma, beta, out);
}

// round 11
// speedup vs baseline: 1.2204x; 1.2204x over previous
#include <cuda_runtime.h>
#include <cuda_bf16.h>
#include <cstdint>

// Problem constants (fixed by dataset)
#define BATCH 16
#define NNODE 16384
#define DIM   128
#define NEDGE 65536
#define TOTAL_NODES (BATCH * NNODE)   // 262144
#define LN_EPS 1e-5f

// ---------------- device scratch (no allocs allowed) ----------------
__device__ __align__(16) float g_neigh[(size_t)TOTAL_NODES * DIM];   // aggregated features
__device__ __align__(16) float g_WT[256 * 128];                      // [Wself;Wneigh]^T: WT[k][n]
__device__ int   g_deg[NNODE];
__device__ int   g_rowstart[NNODE + 1];
__device__ int   g_cursor[NNODE];
__device__ int   g_csr[NEDGE];

// ---- canonical f32x2 helpers ----
__device__ __forceinline__ unsigned long long pack_dup_f32(float a) {
    unsigned int u = __float_as_uint(a);
    unsigned long long out;
    asm("mov.b64 %0, {%1, %2};" : "=l"(out) : "r"(u), "r"(u));
    return out;
}
__device__ __forceinline__ void unpack_f32x2(unsigned long long in, float& lo, float& hi) {
    unsigned int ulo, uhi;
    asm("mov.b64 {%0, %1}, %2;" : "=r"(ulo), "=r"(uhi) : "l"(in));
    lo = __uint_as_float(ulo);
    hi = __uint_as_float(uhi);
}
__device__ __forceinline__ void fma_f32x2(unsigned long long& d,
                                          unsigned long long a,
                                          unsigned long long b) {
    asm("fma.rn.f32x2 %0, %1, %2, %3;" : "=l"(d) : "l"(a), "l"(b), "l"(d));
}

// ---------------- small setup kernels ----------------
__global__ void zero_kernel() {
    int i = blockIdx.x * blockDim.x + threadIdx.x;
    if (i < NNODE) { g_deg[i] = 0; g_cursor[i] = 0; }
}

// edge_index is int32 on the wire (JAX x64 disabled downcasts jnp.int64 -> int32).
__global__ void count_kernel(const int* __restrict__ edge) {
    int e = blockIdx.x * blockDim.x + threadIdx.x;
    if (e < NEDGE) {
        int dst = edge[NEDGE + e];
        atomicAdd(&g_deg[dst], 1);
    }
}

// single-block exclusive scan over 16384 degrees
__global__ void scan_kernel() {
    __shared__ int sums[1024];
    int t = threadIdx.x;
    int base = t * 16;
    int local[16];
    int s = 0;
#pragma unroll
    for (int i = 0; i < 16; i++) { local[i] = s; s += g_deg[base + i]; }
    sums[t] = s;
    __syncthreads();
    for (int off = 1; off < 1024; off <<= 1) {
        int v = 0;
        if (t >= off) v = sums[t - off];
        __syncthreads();
        sums[t] += v;
        __syncthreads();
    }
    int excl = (t == 0) ? 0 : sums[t - 1];
#pragma unroll
    for (int i = 0; i < 16; i++) g_rowstart[base + i] = excl + local[i];
    if (t == 1023) g_rowstart[NNODE] = sums[1023];
}

__global__ void fill_kernel(const int* __restrict__ edge) {
    int e = blockIdx.x * blockDim.x + threadIdx.x;
    if (e < NEDGE) {
        int src = edge[e];
        int dst = edge[NEDGE + e];
        int pos = atomicAdd(&g_cursor[dst], 1);
        g_csr[g_rowstart[dst] + pos] = src;
    }
}

// transpose + concat weights: WT[k][n], k<128 -> Wself[n][k], k>=128 -> Wneigh[n][k-128]
__global__ void wt_kernel(const float* __restrict__ Ws, const float* __restrict__ Wn) {
    int idx = blockIdx.x * blockDim.x + threadIdx.x;
    if (idx < 256 * 128) {
        int k = idx >> 7, n = idx & 127;
        g_WT[idx] = (k < 128) ? Ws[n * 128 + k] : Wn[n * 128 + (k - 128)];
    }
}

// ---------------- neighbor mean via CSR gather (no heavy atomics) ----------------
__global__ __launch_bounds__(256) void neigh_kernel(const float* __restrict__ x) {
    int gwarp = (blockIdx.x * 256 + threadIdx.x) >> 5;   // one warp per (batch,node)
    int lane = threadIdx.x & 31;
    int b = gwarp >> 14;            // / 16384
    int n = gwarp & (NNODE - 1);
    int s0 = g_rowstart[n];
    int s1 = g_rowstart[n + 1];
    const float* xb = x + ((size_t)b << 14) * DIM;
    float4 acc = make_float4(0.f, 0.f, 0.f, 0.f);
    for (int j = s0; j < s1; j++) {
        int src = g_csr[j];
        float4 v = *(const float4*)(xb + (size_t)src * DIM + lane * 4);
        acc.x += v.x; acc.y += v.y; acc.z += v.z; acc.w += v.w;
    }
    int deg = s1 - s0;
    float inv = 1.0f / (float)(deg > 0 ? deg : 1);
    acc.x *= inv; acc.y *= inv; acc.z *= inv; acc.w *= inv;
    *(float4*)(g_neigh + (size_t)gwarp * DIM + lane * 4) = acc;
}

// ---------------- fused dual-GEMM + bias + LayerNorm + ReLU ----------------
// tile: 128 rows x 128 cols, K=256 (phase 0 = x@WselfT, phase 1 = neigh@WneighT)
// 256 threads, 8x8 micro-tile per thread, packed fma.rn.f32x2 (2 FMA lanes/instr).
__global__ __launch_bounds__(256, 2) void gemm_ln_kernel(
    const float* __restrict__ x,
    const float* __restrict__ bias,
    const float* __restrict__ gamma,
    const float* __restrict__ beta,
    float* __restrict__ out)
{
    __shared__ float As[128 * 16];   // [row][k], stride 16
    __shared__ float Bs[16 * 128];   // [k][n]

    int tid = threadIdx.x;
    int tx = tid & 15;     // col group: cols tx*8 .. tx*8+7
    int ty = tid >> 4;     // row group: rows ty*8 .. ty*8+7
    int row0 = blockIdx.x * 128;

    unsigned long long acc[8][4];    // [row][col-pair], each holds cols {2j, 2j+1}
#pragma unroll
    for (int i = 0; i < 8; i++)
#pragma unroll
        for (int j = 0; j < 4; j++) acc[i][j] = 0ull;

#pragma unroll 1
    for (int phase = 0; phase < 2; ++phase) {
        const float* A = phase ? g_neigh : x;
        int wko = phase * 128;
#pragma unroll 1
        for (int kk = 0; kk < 128; kk += 16) {
            // load A tile: 128 rows x 16 k  (512 float4, 2 per thread)
#pragma unroll
            for (int l = 0; l < 2; l++) {
                int idx = tid + l * 256;
                int r = idx >> 2, q = idx & 3;
                float4 v = *(const float4*)(A + (size_t)(row0 + r) * DIM + kk + q * 4);
                *(float4*)(As + r * 16 + q * 4) = v;
            }
            // load B tile: 16 k-rows x 128 n (coalesced from pre-transposed WT, L2-resident)
#pragma unroll
            for (int l = 0; l < 2; l++) {
                int idx = tid + l * 256;
                int k = idx >> 5, q = idx & 31;
                float4 v = *(const float4*)(g_WT + (size_t)(wko + kk + k) * 128 + q * 4);
                *(float4*)(Bs + k * 128 + q * 4) = v;
            }
            __syncthreads();
#pragma unroll
            for (int k = 0; k < 16; k++) {
                // b row: 8 cols = 4 x f32x2, 16B-aligned shared loads
                ulonglong2 p0 = *(const ulonglong2*)(Bs + k * 128 + tx * 8);
                ulonglong2 p1 = *(const ulonglong2*)(Bs + k * 128 + tx * 8 + 4);
                unsigned long long b[4] = { p0.x, p0.y, p1.x, p1.y };
#pragma unroll
                for (int i = 0; i < 8; i++) {
                    unsigned long long a2 = pack_dup_f32(As[(ty * 8 + i) * 16 + k]);
#pragma unroll
                    for (int j = 0; j < 4; j++) fma_f32x2(acc[i][j], a2, b[j]);
                }
            }
            __syncthreads();
        }
    }

    // epilogue: bias -> LayerNorm over 128 cols (16 contiguous lanes per row) -> relu
    float bi[8], ga[8], be[8];
#pragma unroll
    for (int j = 0; j < 8; j++) {
        int col = tx * 8 + j;
        bi[j] = bias[col]; ga[j] = gamma[col]; be[j] = beta[col];
    }

#pragma unroll
    for (int i = 0; i < 8; i++) {
        float c[8];
#pragma unroll
        for (int j = 0; j < 4; j++) unpack_f32x2(acc[i][j], c[2 * j], c[2 * j + 1]);
#pragma unroll
        for (int j = 0; j < 8; j++) c[j] += bi[j];

        float s = 0.f;
#pragma unroll
        for (int j = 0; j < 8; j++) s += c[j];
#pragma unroll
        for (int m = 1; m < 16; m <<= 1) s += __shfl_xor_sync(0xffffffffu, s, m);
        float mean = s * (1.0f / 128.0f);

        float sq = 0.f;
#pragma unroll
        for (int j = 0; j < 8; j++) { float d = c[j] - mean; sq += d * d; }
#pragma unroll
        for (int m = 1; m < 16; m <<= 1) sq += __shfl_xor_sync(0xffffffffu, sq, m);
        float rstd = rsqrtf(sq * (1.0f / 128.0f) + LN_EPS);

        float4 o0, o1;
        float v;
        v = (c[0] - mean) * rstd * ga[0] + be[0]; o0.x = fmaxf(v, 0.f);
        v = (c[1] - mean) * rstd * ga[1] + be[1]; o0.y = fmaxf(v, 0.f);
        v = (c[2] - mean) * rstd * ga[2] + be[2]; o0.z = fmaxf(v, 0.f);
        v = (c[3] - mean) * rstd * ga[3] + be[3]; o0.w = fmaxf(v, 0.f);
        v = (c[4] - mean) * rstd * ga[4] + be[4]; o1.x = fmaxf(v, 0.f);
        v = (c[5] - mean) * rstd * ga[5] + be[5]; o1.y = fmaxf(v, 0.f);
        v = (c[6] - mean) * rstd * ga[6] + be[6]; o1.z = fmaxf(v, 0.f);
        v = (c[7] - mean) * rstd * ga[7] + be[7]; o1.w = fmaxf(v, 0.f);

        size_t row = (size_t)(row0 + ty * 8 + i);
        *(float4*)(out + row * DIM + tx * 8)     = o0;
        *(float4*)(out + row * DIM + tx * 8 + 4) = o1;
    }
}

// ---------------- launch ----------------
extern "C" void kernel_launch(void* const* d_in, const int* in_sizes, int n_in,
                              void* d_out, int out_size)
{
    // robust input mapping by element count
    const float* x = nullptr;
    const int* edge = nullptr;          // int32 on the wire
    const float* Ws = nullptr; const float* Wn = nullptr;
    const float* bias = nullptr; const float* gamma = nullptr; const float* beta = nullptr;
    int w_seen = 0, v_seen = 0;
    for (int i = 0; i < n_in; i++) {
        int sz = in_sizes[i];
        if (sz == TOTAL_NODES * DIM) {
            x = (const float*)d_in[i];
        } else if (sz == 2 * NEDGE) {
            edge = (const int*)d_in[i];
        } else if (sz == 128 * 128) {
            if (w_seen == 0) Ws = (const float*)d_in[i];
            else             Wn = (const float*)d_in[i];
            w_seen++;
        } else if (sz == 128) {
            if (v_seen == 0)      bias  = (const float*)d_in[i];
            else if (v_seen == 1) gamma = (const float*)d_in[i];
            else                  beta  = (const float*)d_in[i];
            v_seen++;
        }
    }
    float* out = (float*)d_out;

    // 1. CSR build (edge structure is batch-invariant)
    zero_kernel<<<(NNODE + 255) / 256, 256>>>();
    count_kernel<<<(NEDGE + 255) / 256, 256>>>(edge);
    scan_kernel<<<1, 1024>>>();
    fill_kernel<<<(NEDGE + 255) / 256, 256>>>(edge);

    // 2. transpose+concat weights
    wt_kernel<<<(256 * 128 + 255) / 256, 256>>>(Ws, Wn);

    // 3. neighbor mean (gather via CSR, 8 node-warps per block)
    neigh_kernel<<<TOTAL_NODES / 8, 256>>>(x);

    // 4. fused dual-GEMM + bias + LayerNorm + ReLU (f32x2 packed FMA)
    gemm_ln_kernel<<<TOTAL_NODES / 128, 256>>>(x, bias, gamma, beta, out);
}